// round 1
// baseline (speedup 1.0000x reference)
#include <cuda_runtime.h>

#define NN 50000
#define EE 800000
#define IN_DIM 256
#define HID 128
#define OUT_DIM 64
#define WS 129            // padded smem stride for transposed W (odd -> conflict-free transpose)
#define NOFF (NN * OUT_DIM)

// ------------------------- device scratch (static, allowed) -------------------------
__device__ int   g_count[NN];
__device__ int   g_cursor[NN];
__device__ int   g_offsets[NN + 1];
__device__ int   g_srclist[EE];
__device__ int   g_src[EE];
__device__ int   g_dst[EE];
__device__ float g_dis[NN];
__device__ float g_hw1[NN * HID];   // dis[row] * (x @ W1^T)
__device__ float g_hs[NN * HID];    // dis[row] * relu(agg1 + b1)
__device__ float g_g[NN * HID];     // Agg(h)
__device__ int   g_is64;

// ------------------------- f32x2 helpers (Blackwell packed FMA) ---------------------
__device__ __forceinline__ unsigned long long pk2(float a, float b) {
    unsigned long long r;
    asm("mov.b64 %0, {%1, %2};" : "=l"(r) : "f"(a), "f"(b));
    return r;
}
__device__ __forceinline__ unsigned long long fma2(unsigned long long a, unsigned long long b,
                                                   unsigned long long c) {
    unsigned long long d;
    asm("fma.rn.f32x2 %0, %1, %2, %3;" : "=l"(d) : "l"(a), "l"(b), "l"(c));
    return d;
}
__device__ __forceinline__ float2 upk2(unsigned long long a) {
    float2 f;
    asm("mov.b64 {%0, %1}, %2;" : "=f"(f.x), "=f"(f.y) : "l"(a));
    return f;
}

// ------------------------- small setup kernels --------------------------------------
__global__ void init_kernel() {
    int i = blockIdx.x * blockDim.x + threadIdx.x;
    if (i < NN) { g_count[i] = 0; g_cursor[i] = 0; }
}

// Detect int64 vs int32 edge_index layout. If the buffer holds int64 indices in
// [0, NN), every 8-byte read is in range. If it holds int32, an int64 read combines
// two indices -> value ~idx1*2^32, out of range unless the odd word is 0 (p~1/50000).
__global__ void detect_kernel(const void* ei) {
    int lane = threadIdx.x;
    const long long* p = (const long long*)ei;
    int ok = 1;
    for (int i = lane; i < 1024; i += 32) {
        long long v = p[i];
        if (v < 0 || v >= NN) ok = 0;
    }
    unsigned m = __ballot_sync(0xffffffffu, ok);
    if (lane == 0) g_is64 = (m == 0xffffffffu) ? 1 : 0;
}

__global__ void convert_hist_kernel(const void* ei) {
    int i = blockIdx.x * blockDim.x + threadIdx.x;
    if (i >= EE) return;
    int s, d;
    if (g_is64) {
        const long long* p = (const long long*)ei;
        s = (int)p[i];
        d = (int)p[EE + i];
    } else {
        const int* p = (const int*)ei;
        s = p[i];
        d = p[EE + i];
    }
    // defensive clamp (indices are valid by construction)
    s = min(max(s, 0), NN - 1);
    d = min(max(d, 0), NN - 1);
    g_src[i] = s;
    g_dst[i] = d;
    atomicAdd(&g_count[d], 1);
}

__global__ void dis_kernel() {
    int i = blockIdx.x * blockDim.x + threadIdx.x;
    if (i < NN) g_dis[i] = rsqrtf((float)(g_count[i] + 1));   // +1 self-loop
}

// single-block exclusive scan of g_count -> g_offsets (incl. total at [NN])
__global__ __launch_bounds__(1024) void scan_kernel() {
    const int T = 1024, PER = (NN + T - 1) / T;   // 49
    int tid = threadIdx.x;
    int base = tid * PER;
    int run = 0;
    for (int i = 0; i < PER; i++) {
        int idx = base + i;
        if (idx < NN) run += g_count[idx];
    }
    __shared__ int wsum[32];
    int lane = tid & 31, wid = tid >> 5;
    int inc = run;
    for (int d = 1; d < 32; d <<= 1) {
        int t = __shfl_up_sync(0xffffffffu, inc, d);
        if (lane >= d) inc += t;
    }
    if (lane == 31) wsum[wid] = inc;
    __syncthreads();
    if (wid == 0) {
        int w = wsum[lane];
        for (int d = 1; d < 32; d <<= 1) {
            int t = __shfl_up_sync(0xffffffffu, w, d);
            if (lane >= d) w += t;
        }
        wsum[lane] = w;
    }
    __syncthreads();
    int warpbase = (wid == 0) ? 0 : wsum[wid - 1];
    int ex = warpbase + inc - run;   // exclusive prefix for this thread
    int acc = ex;
    for (int i = 0; i < PER; i++) {
        int idx = base + i;
        if (idx <= NN) {
            g_offsets[idx] = acc;
            if (idx < NN) acc += g_count[idx];
        }
    }
}

__global__ void scatter_kernel() {
    int i = blockIdx.x * blockDim.x + threadIdx.x;
    if (i >= EE) return;
    int d = g_dst[i];
    int pos = g_offsets[d] + atomicAdd(&g_cursor[d], 1);
    g_srclist[pos] = g_src[i];
}

// ------------------------- GEMM1: g_hw1 = dis[row] * (x @ W1^T) ----------------------
// Wsm[k*WS + o] = W1[o][k], stride 129 (conflict-free transpose + column reads).
// 8 warps * 8 rows/warp = 64-row x tile staged in smem; f32x2 packed FMA.
__global__ __launch_bounds__(256, 1)
void gemm1_kernel(const float* __restrict__ x, const float* __restrict__ W1) {
    extern __shared__ float sm[];
    float* Wsm = sm;                        // [256][129]
    float* xsm = sm + IN_DIM * WS;          // [64][256]
    int tid = threadIdx.x, lane = tid & 31, warp = tid >> 5;

    for (int o = warp; o < HID; o += 8) {
#pragma unroll
        for (int m = 0; m < IN_DIM / 32; m++) {
            int k = m * 32 + lane;
            Wsm[k * WS + o] = W1[o * IN_DIM + k];
        }
    }
    __syncthreads();

    const int RB = 64;
    int nblk = (NN + RB - 1) / RB;
    for (int blk = blockIdx.x; blk < nblk; blk += gridDim.x) {
        int row0 = blk * RB;
        __syncthreads();
#pragma unroll
        for (int i = 0; i < 16; i++) {           // 4096 float4 = 64x256
            int lin = tid + 256 * i;
            int r = lin >> 6, c4 = lin & 63;
            int row = row0 + r;
            float4 v = make_float4(0.f, 0.f, 0.f, 0.f);
            if (row < NN) v = ((const float4*)x)[row * (IN_DIM / 4) + c4];
            ((float4*)xsm)[r * (IN_DIM / 4) + c4] = v;
        }
        __syncthreads();

        unsigned long long acc[8][2];
#pragma unroll
        for (int r = 0; r < 8; r++) { acc[r][0] = 0ULL; acc[r][1] = 0ULL; }
        const float* xw = xsm + (warp * 8) * IN_DIM;

#pragma unroll 4
        for (int k = 0; k < IN_DIM; k++) {
            const float* wk = Wsm + k * WS;
            unsigned long long wp0 = pk2(wk[lane], wk[lane + 32]);
            unsigned long long wp1 = pk2(wk[lane + 64], wk[lane + 96]);
#pragma unroll
            for (int r = 0; r < 8; r++) {
                float xv = xw[r * IN_DIM + k];
                unsigned long long xp = pk2(xv, xv);
                acc[r][0] = fma2(xp, wp0, acc[r][0]);
                acc[r][1] = fma2(xp, wp1, acc[r][1]);
            }
        }
#pragma unroll
        for (int r = 0; r < 8; r++) {
            int row = row0 + warp * 8 + r;
            if (row < NN) {
                float di = g_dis[row];
                float2 a01 = upk2(acc[r][0]);
                float2 a23 = upk2(acc[r][1]);
                float* orow = g_hw1 + row * HID;
                orow[lane]      = di * a01.x;
                orow[lane + 32] = di * a01.y;
                orow[lane + 64] = di * a23.x;
                orow[lane + 96] = di * a23.y;
            }
        }
    }
}

// ------------------------- aggregation: warp per destination node -------------------
// feat rows are pre-scaled by dis[src]; out[i] = di*(sum_in feat[s] + feat[i]) [+b,relu,*di]
template <bool RELU>
__device__ __forceinline__ void agg_body(const float* __restrict__ feat,
                                         float* __restrict__ out,
                                         const float* __restrict__ bias) {
    int gw = (blockIdx.x * blockDim.x + threadIdx.x) >> 5;
    int lane = threadIdx.x & 31;
    if (gw >= NN) return;
    int beg = g_offsets[gw], end = g_offsets[gw + 1];
    const float4* f4 = (const float4*)feat;
    float4 acc = f4[gw * 32 + lane];      // self-loop term
    int p = beg;
    for (; p + 1 < end; p += 2) {
        int s0 = g_srclist[p], s1 = g_srclist[p + 1];
        float4 v0 = f4[s0 * 32 + lane];
        float4 v1 = f4[s1 * 32 + lane];
        acc.x += v0.x; acc.y += v0.y; acc.z += v0.z; acc.w += v0.w;
        acc.x += v1.x; acc.y += v1.y; acc.z += v1.z; acc.w += v1.w;
    }
    if (p < end) {
        int s = g_srclist[p];
        float4 v = f4[s * 32 + lane];
        acc.x += v.x; acc.y += v.y; acc.z += v.z; acc.w += v.w;
    }
    float di = g_dis[gw];
    float4 r;
    if (RELU) {
        float4 b = ((const float4*)bias)[lane];
        r.x = di * fmaxf(fmaf(di, acc.x, b.x), 0.f);
        r.y = di * fmaxf(fmaf(di, acc.y, b.y), 0.f);
        r.z = di * fmaxf(fmaf(di, acc.z, b.z), 0.f);
        r.w = di * fmaxf(fmaf(di, acc.w, b.w), 0.f);
    } else {
        r.x = di * acc.x; r.y = di * acc.y; r.z = di * acc.z; r.w = di * acc.w;
    }
    ((float4*)out)[gw * 32 + lane] = r;
}

__global__ __launch_bounds__(256) void agg1_kernel(const float* __restrict__ b1) {
    agg_body<true>(g_hw1, g_hs, b1);
}
__global__ __launch_bounds__(256) void agg2_kernel() {
    agg_body<false>(g_hs, g_g, nullptr);
}

// ------------------------- GEMM2: [mu | lv] = g_g @ [Wmu;Wlv]^T + [bmu;blv] ----------
__global__ __launch_bounds__(256, 2)
void gemm2_kernel(const float* __restrict__ Wmu, const float* __restrict__ bmu,
                  const float* __restrict__ Wlv, const float* __restrict__ blv,
                  float* __restrict__ out) {
    extern __shared__ float sm[];
    float* Wsm = sm;                     // [128][129]
    float* bsm = sm + HID * WS;          // [128]
    float* xsm = bsm + HID;              // [64][128]
    int tid = threadIdx.x, lane = tid & 31, warp = tid >> 5;

    for (int o = warp; o < HID; o += 8) {
#pragma unroll
        for (int m = 0; m < HID / 32; m++) {
            int k = m * 32 + lane;
            float w = (o < OUT_DIM) ? Wmu[o * HID + k] : Wlv[(o - OUT_DIM) * HID + k];
            Wsm[k * WS + o] = w;
        }
    }
    if (tid < HID) bsm[tid] = (tid < OUT_DIM) ? bmu[tid] : blv[tid - OUT_DIM];
    __syncthreads();

    const int RB = 64;
    int nblk = (NN + RB - 1) / RB;
    for (int blk = blockIdx.x; blk < nblk; blk += gridDim.x) {
        int row0 = blk * RB;
        __syncthreads();
#pragma unroll
        for (int i = 0; i < 8; i++) {            // 2048 float4 = 64x128
            int lin = tid + 256 * i;
            int r = lin >> 5, c4 = lin & 31;
            int row = row0 + r;
            float4 v = make_float4(0.f, 0.f, 0.f, 0.f);
            if (row < NN) v = ((const float4*)g_g)[row * (HID / 4) + c4];
            ((float4*)xsm)[r * (HID / 4) + c4] = v;
        }
        __syncthreads();

        unsigned long long acc[8][2];
#pragma unroll
        for (int r = 0; r < 8; r++) { acc[r][0] = 0ULL; acc[r][1] = 0ULL; }
        const float* xw = xsm + (warp * 8) * HID;

#pragma unroll 4
        for (int k = 0; k < HID; k++) {
            const float* wk = Wsm + k * WS;
            unsigned long long wp0 = pk2(wk[lane], wk[lane + 32]);
            unsigned long long wp1 = pk2(wk[lane + 64], wk[lane + 96]);
#pragma unroll
            for (int r = 0; r < 8; r++) {
                float xv = xw[r * HID + k];
                unsigned long long xp = pk2(xv, xv);
                acc[r][0] = fma2(xp, wp0, acc[r][0]);
                acc[r][1] = fma2(xp, wp1, acc[r][1]);
            }
        }
#pragma unroll
        for (int r = 0; r < 8; r++) {
            int row = row0 + warp * 8 + r;
            if (row < NN) {
                float2 a01 = upk2(acc[r][0]);   // mu cols lane, lane+32
                float2 a23 = upk2(acc[r][1]);   // lv cols lane, lane+32
                out[row * OUT_DIM + lane]            = a01.x + bsm[lane];
                out[row * OUT_DIM + lane + 32]       = a01.y + bsm[lane + 32];
                out[NOFF + row * OUT_DIM + lane]      = a23.x + bsm[lane + 64];
                out[NOFF + row * OUT_DIM + lane + 32] = a23.y + bsm[lane + 96];
            }
        }
    }
}

// ------------------------- launch --------------------------------------------------
extern "C" void kernel_launch(void* const* d_in, const int* in_sizes, int n_in,
                              void* d_out, int out_size) {
    const float* x   = (const float*)d_in[0];
    const void*  ei  = d_in[1];
    const float* W1  = (const float*)d_in[2];
    const float* b1  = (const float*)d_in[3];
    const float* Wmu = (const float*)d_in[4];
    const float* bmu = (const float*)d_in[5];
    const float* Wlv = (const float*)d_in[6];
    const float* blv = (const float*)d_in[7];
    float* out = (float*)d_out;

    const int SMEM1 = (IN_DIM * WS + 64 * IN_DIM) * (int)sizeof(float);   // 197,632 B
    const int SMEM2 = (HID * WS + HID + 64 * HID) * (int)sizeof(float);   //  99,328 B
    cudaFuncSetAttribute(gemm1_kernel, cudaFuncAttributeMaxDynamicSharedMemorySize, SMEM1);
    cudaFuncSetAttribute(gemm2_kernel, cudaFuncAttributeMaxDynamicSharedMemorySize, SMEM2);

    init_kernel<<<(NN + 255) / 256, 256>>>();
    detect_kernel<<<1, 32>>>(ei);
    convert_hist_kernel<<<(EE + 255) / 256, 256>>>(ei);
    dis_kernel<<<(NN + 255) / 256, 256>>>();
    scan_kernel<<<1, 1024>>>();
    scatter_kernel<<<(EE + 255) / 256, 256>>>();

    gemm1_kernel<<<148, 256, SMEM1>>>(x, W1);

    int agg_blocks = (NN * 32 + 255) / 256;   // one warp per node
    agg1_kernel<<<agg_blocks, 256>>>(b1);
    agg2_kernel<<<agg_blocks, 256>>>();

    gemm2_kernel<<<296, 256, SMEM2>>>(Wmu, bmu, Wlv, blv, out);
}